// round 4
// baseline (speedup 1.0000x reference)
#include <cuda_runtime.h>

// PWLU channelwise activation, scalar bounds ±2.3, n_points=7 (n_regions=6).
// x: [B=64, C=256, H=56, W=56] fp32; points: [C,7]; left_diffs/right_diffs: [C].
// out = fp[c][r] + (xn - r) * df[c][r],  xn=(x-sim_left)/region_len, r=clip int.
//
// R3: R1 shape (front-batch loads, then compute+store, exit) but each CTA
// covers TWO batch-slices of the same channel (b and b+32): 6-8 LDG.128 in
// flight per warp before any dependent work. Default cache ops (no .cs).

#define BOUND_F 2.3f
#define N_POINTS 7
#define N_REGIONS 6
#define C_DIM 256
#define HW 3136            // 56*56
#define HW4 784            // float4 per slice
#define THREADS 256
#define B_DIM 64

__global__ __launch_bounds__(THREADS)
void pwlu_kernel(const float* __restrict__ x,
                 const float* __restrict__ points,
                 const float* __restrict__ left_diffs,
                 const float* __restrict__ right_diffs,
                 float* __restrict__ out) {
    const int bx  = blockIdx.x;             // b*C + c, b in [0,32)
    const int c   = bx & (C_DIM - 1);
    const int b   = bx >> 8;                // [0,32)
    const int tid = threadIdx.x;

    // Per-channel (false_point, diff) table in shared memory.
    __shared__ float2 tab[8];               // tab[r] = {fp[r], df[r]}
    if (tid < 8) {
        const float* p = points + c * N_POINTS;
        float fp, df;
        if (tid == 0)            { df = left_diffs[c];  fp = p[0] - df; }
        else if (tid == N_POINTS){ df = right_diffs[c]; fp = p[N_POINTS - 1]; }
        else                     { df = p[tid] - p[tid - 1]; fp = p[tid - 1]; }
        tab[tid] = make_float2(fp, df);
    }
    __syncthreads();

    const float region_len = (2.0f * BOUND_F) / (float)N_REGIONS;
    const float inv_rl     = (float)N_REGIONS / (2.0f * BOUND_F);
    const float sim_left   = -BOUND_F - region_len;
    const float clip_hi    = (float)(N_REGIONS + 1) * 1.001f;   // 7.007

    const size_t base0 = ((size_t)bx) * HW;                       // slice (b, c)
    const size_t base1 = ((size_t)(bx + 32 * C_DIM)) * HW;        // slice (b+32, c)
    const float4* __restrict__ xin0 = reinterpret_cast<const float4*>(x + base0);
    const float4* __restrict__ xin1 = reinterpret_cast<const float4*>(x + base1);
    float4* __restrict__ o0 = reinterpret_cast<float4*>(out + base0);
    float4* __restrict__ o1 = reinterpret_cast<float4*>(out + base1);

    // 784 float4 per slice: tid, +256, +512 always valid; +768 valid tid<16.
    // Front-batch all loads (up to 8 LDG.128 in flight) before any compute.
    const bool tail = (tid < HW4 - 768);    // tid < 16
    float4 a0 = xin0[tid];
    float4 a1 = xin0[tid + 256];
    float4 a2 = xin0[tid + 512];
    float4 b0 = xin1[tid];
    float4 b1 = xin1[tid + 256];
    float4 b2 = xin1[tid + 512];
    float4 a3, b3;
    if (tail) { a3 = xin0[tid + 768]; b3 = xin1[tid + 768]; }

    auto pwlu1 = [&](float xv) -> float {
        float xn = (xv - sim_left) * inv_rl;
        float rf = fminf(fmaxf(xn, 0.0f), clip_hi);
        int   r  = __float2int_rz(rf);
        float d  = xn - (float)r;
        float2 t = tab[r];
        return fmaf(d, t.y, t.x);
    };
    auto pwlu4 = [&](float4 v) -> float4 {
        float4 r;
        r.x = pwlu1(v.x); r.y = pwlu1(v.y);
        r.z = pwlu1(v.z); r.w = pwlu1(v.w);
        return r;
    };

    o0[tid]       = pwlu4(a0);
    o0[tid + 256] = pwlu4(a1);
    o0[tid + 512] = pwlu4(a2);
    o1[tid]       = pwlu4(b0);
    o1[tid + 256] = pwlu4(b1);
    o1[tid + 512] = pwlu4(b2);
    if (tail) {
        o0[tid + 768] = pwlu4(a3);
        o1[tid + 768] = pwlu4(b3);
    }
}

extern "C" void kernel_launch(void* const* d_in, const int* in_sizes, int n_in,
                              void* d_out, int out_size) {
    const float* x  = (const float*)d_in[0];
    const float* p  = (const float*)d_in[1];
    const float* ld = (const float*)d_in[2];
    const float* rd = (const float*)d_in[3];
    float* out = (float*)d_out;

    const int n_blocks = (B_DIM / 2) * C_DIM;   // 8192
    pwlu_kernel<<<n_blocks, THREADS>>>(x, p, ld, rd, out);
}

// round 6
// speedup vs baseline: 1.0570x; 1.0570x over previous
#include <cuda_runtime.h>

// PWLU channelwise activation, scalar bounds ±2.3, n_points=7 (n_regions=6).
// x: [B=64, C=256, H=56, W=56] fp32; points: [C,7]; left_diffs/right_diffs: [C].
// out = fp[c][r] + (xn - r) * df[c][r],  xn=(x-sim_left)/region_len, r=clip int.
//
// R4: exact R1 structure (one CTA per (b,c) slice; front-batch 3-4 LDG.128,
// compute, store, exit) + ONE change: evict-first streaming stores (__stcs).
// Output is write-once/never-read; evict-first lets L2 drain dirty lines
// steadily instead of in bursts that contend with the read stream.

#define BOUND_F 2.3f
#define N_POINTS 7
#define N_REGIONS 6
#define C_DIM 256
#define HW 3136            // 56*56
#define HW4 784            // HW/4
#define THREADS 256

__global__ __launch_bounds__(THREADS)
void pwlu_kernel(const float* __restrict__ x,
                 const float* __restrict__ points,
                 const float* __restrict__ left_diffs,
                 const float* __restrict__ right_diffs,
                 float* __restrict__ out) {
    const int bc = blockIdx.x;          // b*C + c
    const int c  = bc & (C_DIM - 1);
    const int tid = threadIdx.x;

    // Build the per-channel (false_point, diff) table in shared memory.
    __shared__ float2 tab[8];           // tab[r] = {fp[r], df[r]}
    if (tid < 8) {
        const float* p = points + c * N_POINTS;
        float fp, df;
        if (tid == 0)            { df = left_diffs[c];  fp = p[0] - df; }
        else if (tid == N_POINTS){ df = right_diffs[c]; fp = p[N_POINTS - 1]; }
        else                     { df = p[tid] - p[tid - 1]; fp = p[tid - 1]; }
        tab[tid] = make_float2(fp, df);
    }
    __syncthreads();

    const float region_len = (2.0f * BOUND_F) / (float)N_REGIONS;
    const float inv_rl     = (float)N_REGIONS / (2.0f * BOUND_F);
    const float sim_left   = -BOUND_F - region_len;
    const float clip_hi    = (float)(N_REGIONS + 1) * 1.001f;   // 7.007

    const float4* __restrict__ xin = reinterpret_cast<const float4*>(x + (size_t)bc * HW);
    float4* __restrict__ o         = reinterpret_cast<float4*>(out + (size_t)bc * HW);

    // 784 float4 per block, 256 threads: indices tid, tid+256, tid+512 always
    // valid; tid+768 valid for tid < 16. Front-batch loads for MLP.
    float4 v0 = xin[tid];
    float4 v1 = xin[tid + 256];
    float4 v2 = xin[tid + 512];
    float4 v3;
    const bool has3 = (tid < HW4 - 768);
    if (has3) v3 = xin[tid + 768];

    auto pwlu1 = [&](float xv) -> float {
        float xn = (xv - sim_left) * inv_rl;
        float rf = fminf(fmaxf(xn, 0.0f), clip_hi);
        int   r  = __float2int_rz(rf);
        float d  = xn - (float)r;
        float2 t = tab[r];
        return fmaf(d, t.y, t.x);
    };
    auto pwlu4 = [&](float4 v) -> float4 {
        float4 r;
        r.x = pwlu1(v.x); r.y = pwlu1(v.y);
        r.z = pwlu1(v.z); r.w = pwlu1(v.w);
        return r;
    };

    __stcs(&o[tid],       pwlu4(v0));
    __stcs(&o[tid + 256], pwlu4(v1));
    __stcs(&o[tid + 512], pwlu4(v2));
    if (has3) __stcs(&o[tid + 768], pwlu4(v3));
}

extern "C" void kernel_launch(void* const* d_in, const int* in_sizes, int n_in,
                              void* d_out, int out_size) {
    const float* x  = (const float*)d_in[0];
    const float* p  = (const float*)d_in[1];
    const float* ld = (const float*)d_in[2];
    const float* rd = (const float*)d_in[3];
    float* out = (float*)d_out;

    const int B = 64;
    const int n_blocks = B * C_DIM;     // 16384
    pwlu_kernel<<<n_blocks, THREADS>>>(x, p, ld, rd, out);
}